// round 3
// baseline (speedup 1.0000x reference)
#include <cuda_runtime.h>
#include <math.h>

#define NBATCH 64
#define NPTS   500
#define DIM    2048
#define KCL    10
#define NITER  10
#define EPSV   1e-6f
#define NSPLIT 2
#define NROWC  (NPTS / NSPLIT)   // 250
#define TILE   64

// ---------------- persistent device scratch ----------------
__device__ float g_part[NBATCH * NSPLIT * KCL * DIM];   // per-CTA partial sums
__device__ int   g_pcnt[NBATCH * NSPLIT * KCL];
__device__ int   g_assign[NBATCH * NPTS];

// ---------------- packed f32x2 helpers ----------------
__device__ __forceinline__ unsigned long long fma2(unsigned long long a,
                                                   unsigned long long b,
                                                   unsigned long long c) {
    unsigned long long d;
    asm("fma.rn.f32x2 %0, %1, %2, %3;" : "=l"(d) : "l"(a), "l"(b), "l"(c));
    return d;
}
__device__ __forceinline__ float2 unpack2(unsigned long long v) {
    float2 r;
    asm("mov.b64 {%0, %1}, %2;" : "=f"(r.x), "=f"(r.y) : "l"(v));
    return r;
}

// ---------------- init: partial slot0 = features[:, :K, :], cnt=1; slot1=0 ----
__global__ void init_kernel(const float* __restrict__ f) {
    int b = blockIdx.x / KCL, k = blockIdx.x % KCL;
    int d = threadIdx.x * 4;
    float4 v = *(const float4*)(f + ((size_t)(b * NPTS + k)) * DIM + d);
    *(float4*)(g_part + ((size_t)((b * 2 + 0) * KCL + k)) * DIM + d) = v;
    *(float4*)(g_part + ((size_t)((b * 2 + 1) * KCL + k)) * DIM + d) =
        make_float4(0.f, 0.f, 0.f, 0.f);
    if (threadIdx.x == 0) {
        g_pcnt[(b * 2 + 0) * KCL + k] = 1;
        g_pcnt[(b * 2 + 1) * KCL + k] = 0;
    }
}

// FMA block: same-acc updates spaced 4 instructions apart (lat-4 friendly)
#define FMABLOCK(C0, C1, C2, C3)                                              \
    _Pragma("unroll")                                                         \
    for (int k = 0; k < KCL; k++) {                                           \
        ulonglong2 cc = *(const ulonglong2*)(scd + (size_t)k * DIM);          \
        acc[k][0] = fma2((C0).x, cc.x, acc[k][0]);                            \
        acc[k][1] = fma2((C1).x, cc.x, acc[k][1]);                            \
        acc[k][2] = fma2((C2).x, cc.x, acc[k][2]);                            \
        acc[k][3] = fma2((C3).x, cc.x, acc[k][3]);                            \
        acc[k][0] = fma2((C0).y, cc.y, acc[k][0]);                            \
        acc[k][1] = fma2((C1).y, cc.y, acc[k][1]);                            \
        acc[k][2] = fma2((C2).y, cc.y, acc[k][2]);                            \
        acc[k][3] = fma2((C3).y, cc.y, acc[k][3]);                            \
    }

// ---------------- fused: centroid build + assign + partial update ----------
// grid = 128 (b, sp), block = 512 (16 warps), ~165KB smem, 1 CTA/SM.
__global__ __launch_bounds__(512, 1) void iter_kernel(const float* __restrict__ feats,
                                                      int last) {
    extern __shared__ float smem[];
    float* sc     = smem;                  // [KCL][DIM] centroids
    float* sacc   = smem + KCL * DIM;      // [KCL][DIM] new partial sums
    float* schalf = sacc + KCL * DIM;      // [16]
    float* sinv   = schalf + 16;           // [16]
    int*   sa     = (int*)(sinv + 16);     // [TILE]
    int*   scnt   = sa + TILE;             // [16]

    int b = blockIdx.x >> 1, sp = blockIdx.x & 1;
    int tid = threadIdx.x, warp = tid >> 5, lane = tid & 31;
    float4 z4 = make_float4(0.f, 0.f, 0.f, 0.f);

    if (tid < KCL) {
        int c = g_pcnt[(b * 2 + 0) * KCL + tid] + g_pcnt[(b * 2 + 1) * KCL + tid];
        sinv[tid] = 1.0f / (float)(c > 1 ? c : 1);
        scnt[tid] = 0;
    }
    __syncthreads();

    // centroids = (part0 + part1) * inv ; zero accumulators
    {
        const float4* q0 = (const float4*)(g_part + (size_t)(b * 2 + 0) * KCL * DIM);
        const float4* q1 = (const float4*)(g_part + (size_t)(b * 2 + 1) * KCL * DIM);
        for (int i = tid; i < KCL * DIM / 4; i += 512) {
            float4 a = q0[i], c = q1[i];
            float inv = sinv[i / (DIM / 4)];
            ((float4*)sc)[i] = make_float4((a.x + c.x) * inv, (a.y + c.y) * inv,
                                           (a.z + c.z) * inv, (a.w + c.w) * inv);
            ((float4*)sacc)[i] = z4;
        }
    }
    __syncthreads();

    if (warp < KCL) {
        float s = 0.f;
        for (int d = lane; d < DIM; d += 32) {
            float c = sc[warp * DIM + d];
            s = fmaf(c, c, s);
        }
        #pragma unroll
        for (int o = 16; o; o >>= 1) s += __shfl_xor_sync(0xffffffffu, s, o);
        if (lane == 0) schalf[warp] = 0.5f * s;
    }
    __syncthreads();

    const float* fb = feats + ((size_t)b * NPTS + (size_t)sp * NROWC) * DIM;
    int gabase = b * NPTS + sp * NROWC;
    int mywd = warp * 128 + lane * 4;          // phase-B d-slice (float4)

    for (int tbase = 0; tbase < NROWC; tbase += TILE) {
        // ---------- phase A: assign 4 rows per warp ----------
        int r0i = tbase + warp * 4;
        int i0 = min(r0i + 0, NROWC - 1);
        int i1 = min(r0i + 1, NROWC - 1);
        int i2 = min(r0i + 2, NROWC - 1);
        int i3 = min(r0i + 3, NROWC - 1);
        const float* p0 = fb + (size_t)i0 * DIM + lane * 4;
        const float* p1 = fb + (size_t)i1 * DIM + lane * 4;
        const float* p2 = fb + (size_t)i2 * DIM + lane * 4;
        const float* p3 = fb + (size_t)i3 * DIM + lane * 4;

        unsigned long long acc[KCL][4];
        #pragma unroll
        for (int k = 0; k < KCL; k++)
            #pragma unroll
            for (int r = 0; r < 4; r++) acc[k][r] = 0ull;

        ulonglong2 c0 = *(const ulonglong2*)p0;
        ulonglong2 c1 = *(const ulonglong2*)p1;
        ulonglong2 c2 = *(const ulonglong2*)p2;
        ulonglong2 c3 = *(const ulonglong2*)p3;
        #pragma unroll 1
        for (int ch = 0; ch < 15; ch++) {
            int nofs = (ch + 1) * 128;
            ulonglong2 n0 = *(const ulonglong2*)(p0 + nofs);
            ulonglong2 n1 = *(const ulonglong2*)(p1 + nofs);
            ulonglong2 n2 = *(const ulonglong2*)(p2 + nofs);
            ulonglong2 n3 = *(const ulonglong2*)(p3 + nofs);
            const float* scd = sc + ch * 128 + lane * 4;
            FMABLOCK(c0, c1, c2, c3);
            c0 = n0; c1 = n1; c2 = n2; c3 = n3;
        }
        {
            const float* scd = sc + 15 * 128 + lane * 4;
            FMABLOCK(c0, c1, c2, c3);
        }

        float dot[KCL][4];
        #pragma unroll
        for (int k = 0; k < KCL; k++) {
            #pragma unroll
            for (int r = 0; r < 4; r++) {
                float2 v = unpack2(acc[k][r]);
                float s = v.x + v.y;
                #pragma unroll
                for (int o = 16; o; o >>= 1)
                    s += __shfl_xor_sync(0xffffffffu, s, o);
                dot[k][r] = s;
            }
        }
        #pragma unroll
        for (int r = 0; r < 4; r++) {
            if (lane == r) {
                float best = schalf[0] - dot[0][r];
                int bi = 0;
                #pragma unroll
                for (int k = 1; k < KCL; k++) {
                    float s = schalf[k] - dot[k][r];
                    if (s < best) { best = s; bi = k; }
                }
                bool valid = (r0i + r) < NROWC;
                sa[warp * 4 + r] = valid ? bi : -1;
                if (valid) g_assign[gabase + r0i + r] = bi;
            }
        }
        __syncthreads();

        // ---------- phase B: per-warp ballot masks, accumulate slices ----------
        {
            int a0 = sa[lane];
            int a1 = sa[32 + lane];
            const float* fsl = fb + (size_t)tbase * DIM + mywd;
            #pragma unroll
            for (int k = 0; k < KCL; k++) {
                unsigned m0 = __ballot_sync(0xffffffffu, a0 == k);
                unsigned m1 = __ballot_sync(0xffffffffu, a1 == k);
                if (warp == 0 && lane == 0) scnt[k] += __popc(m0) + __popc(m1);
                if (m0 | m1) {
                    float4 a4 = z4;
                    unsigned mm = m0;
                    while (mm) {
                        int n = __ffs(mm) - 1; mm &= mm - 1;
                        float4 f = *(const float4*)(fsl + (size_t)n * DIM);
                        a4.x += f.x; a4.y += f.y; a4.z += f.z; a4.w += f.w;
                    }
                    mm = m1;
                    while (mm) {
                        int n = __ffs(mm) + 31; mm &= mm - 1;
                        float4 f = *(const float4*)(fsl + (size_t)n * DIM);
                        a4.x += f.x; a4.y += f.y; a4.z += f.z; a4.w += f.w;
                    }
                    float4* ap = (float4*)(sacc + (size_t)k * DIM + mywd);
                    float4 cur = *ap;
                    cur.x += a4.x; cur.y += a4.y; cur.z += a4.z; cur.w += a4.w;
                    *ap = cur;
                }
            }
        }
        __syncthreads();
    }

    // write partials + counts for next iteration
    float* pb = g_part + (size_t)blockIdx.x * KCL * DIM;
    for (int i = tid; i < KCL * DIM / 4; i += 512)
        ((float4*)pb)[i] = ((const float4*)sacc)[i];
    if (tid < KCL) g_pcnt[blockIdx.x * KCL + tid] = scnt[tid];
}

// ---------------- final GeM pooling (empty cluster -> 0) ----------------
__global__ __launch_bounds__(512) void final_kernel(const float* __restrict__ feats,
                                                    const float* __restrict__ pp,
                                                    float* __restrict__ out) {
    __shared__ int sa[NPTS];
    int b = blockIdx.x / KCL, k = blockIdx.x % KCL;
    int tid = threadIdx.x;
    for (int i = tid; i < NPTS; i += 512) sa[i] = g_assign[b * NPTS + i];
    __syncthreads();

    float pv = pp[0];
    bool p3 = (pv == 3.0f);
    const float* fb = feats + (size_t)b * NPTS * DIM + tid * 4;

    float ax = 0.f, ay = 0.f, az = 0.f, aw = 0.f;
    int cnt = 0;
    if (p3) {
        #pragma unroll 2
        for (int n = 0; n < NPTS; n++) {
            if (sa[n] == k) {
                cnt++;
                float4 f = *(const float4*)(fb + (size_t)n * DIM);
                float x = fmaxf(f.x, EPSV), y = fmaxf(f.y, EPSV);
                float z = fmaxf(f.z, EPSV), w = fmaxf(f.w, EPSV);
                ax += x * x * x; ay += y * y * y; az += z * z * z; aw += w * w * w;
            }
        }
    } else {
        for (int n = 0; n < NPTS; n++) {
            if (sa[n] == k) {
                cnt++;
                float4 f = *(const float4*)(fb + (size_t)n * DIM);
                ax += powf(fmaxf(f.x, EPSV), pv);
                ay += powf(fmaxf(f.y, EPSV), pv);
                az += powf(fmaxf(f.z, EPSV), pv);
                aw += powf(fmaxf(f.w, EPSV), pv);
            }
        }
    }

    float inv = 1.0f / (float)(cnt > 1 ? cnt : 1);
    size_t oi = (size_t)(b * KCL + k) * DIM + tid * 4;
    float4 o;
    if (cnt > 0) {
        if (p3) {
            o = make_float4(cbrtf(ax * inv), cbrtf(ay * inv),
                            cbrtf(az * inv), cbrtf(aw * inv));
        } else {
            float ip = 1.0f / pv;
            o = make_float4(powf(ax * inv, ip), powf(ay * inv, ip),
                            powf(az * inv, ip), powf(aw * inv, ip));
        }
    } else {
        o = make_float4(0.f, 0.f, 0.f, 0.f);   // empty cluster: centroid == 0
    }
    *(float4*)(out + oi) = o;
}

// ---------------- launch ----------------
extern "C" void kernel_launch(void* const* d_in, const int* in_sizes, int n_in,
                              void* d_out, int out_size) {
    const float* feats = (const float*)d_in[0];
    const float* p     = (const float*)d_in[1];
    float* out         = (float*)d_out;

    const int smem_iter = (2 * KCL * DIM + 32) * sizeof(float)
                        + (TILE + 16) * sizeof(int);
    cudaFuncSetAttribute(iter_kernel,
                         cudaFuncAttributeMaxDynamicSharedMemorySize, smem_iter);

    init_kernel<<<NBATCH * KCL, 512>>>(feats);
    for (int it = 0; it < NITER; it++)
        iter_kernel<<<NBATCH * NSPLIT, 512, smem_iter>>>(feats, it == NITER - 1);
    final_kernel<<<NBATCH * KCL, 512>>>(feats, p, out);
}